// round 8
// baseline (speedup 1.0000x reference)
#include <cuda_runtime.h>
#include <math.h>

// ---------------------------------------------------------------------------
// Scratch (__device__ globals; no allocation allowed).
// ---------------------------------------------------------------------------
#define MAX_TILES 16384
struct TileState {
    int   flag;            // 0=invalid, 1=aggregate ready, 2=inclusive ready
    float am, as;          // tile aggregate   (sum alpha^t*mu, sum alpha^t*sigma)
    float im, is;          // inclusive prefix (through this tile)
    int   pad[3];          // pad to 32B
};
__device__ TileState g_state[MAX_TILES];
__device__ unsigned int g_ticket;

// fallback-path scratch
#define MAX_ROWS (1 << 17)
__device__ float2 g_stats[MAX_ROWS];
__device__ float2 g_cum[MAX_ROWS];

// ---------------------------------------------------------------------------
// Init kernel: reset lookback state + ticket each launch (graph replays!).
// ---------------------------------------------------------------------------
__global__ void init_kernel(int ntiles) {
    int i = blockIdx.x * blockDim.x + threadIdx.x;
    if (i < ntiles) g_state[i].flag = 0;
    if (i == 0) g_ticket = 0u;
}

// ---------------------------------------------------------------------------
// Fused single-pass kernel. 128 threads, tile = 8 rows of D floats.
// thread t -> row = t>>4 in tile, 16 threads/row, each holds NF4 float4.
// NF4 = D/64. Small CTA => ~8 CTAs/SM resident => phases of different CTAs
// (load / scan+lookback / store) overlap to keep HBM saturated.
// ---------------------------------------------------------------------------
template <int NF4>
__global__ __launch_bounds__(128)
void fused_kernel(const float* __restrict__ x,
                  const float* __restrict__ h,
                  const float* __restrict__ gamma,
                  const float* __restrict__ beta,
                  const float* __restrict__ alogit,
                  float* __restrict__ y,
                  float* __restrict__ out_h,
                  int S, int D, int tilesPerBatch)
{
    __shared__ float4 s_gamma[256];           // supports D <= 1024
    __shared__ float4 s_beta[256];
    __shared__ float  s_mu[8], s_sig[8];
    __shared__ float  s_rowmu[8], s_rowinv[8];
    __shared__ unsigned s_vid;

    const int tid = threadIdx.x;
    const int D4  = D >> 2;

    // stage gamma/beta
    for (int i = tid; i < D4; i += 128) {
        s_gamma[i] = reinterpret_cast<const float4*>(gamma)[i];
        s_beta[i]  = reinterpret_cast<const float4*>(beta)[i];
    }
    if (tid == 0) s_vid = atomicAdd(&g_ticket, 1u);
    __syncthreads();

    const int vid = (int)s_vid;
    const int b   = vid / tilesPerBatch;
    const int j   = vid - b * tilesPerBatch;
    const int s0  = j * 8;

    const float alpha = 1.f / (1.f + expf(-alogit[0]));
    const float one_minus = 1.f - alpha;

    const int rowInTile = tid >> 4;          // 0..7
    const int lane16    = tid & 15;
    const int s         = s0 + rowInTile;
    const bool rowValid = (s < S);

    // ---- load tile into registers, per-thread partial stats ----
    const size_t rowBase = ((size_t)b * S + s) * (size_t)D4;   // float4 units
    float4 v[NF4];
    float sum = 0.f, sq = 0.f;
    if (rowValid) {
#pragma unroll
        for (int i = 0; i < NF4; i++)
            v[i] = __ldcs(reinterpret_cast<const float4*>(x) + rowBase + lane16 + (i << 4));
#pragma unroll
        for (int i = 0; i < NF4; i++) {
            sum += (v[i].x + v[i].y) + (v[i].z + v[i].w);
            sq  += (v[i].x * v[i].x + v[i].y * v[i].y) +
                   (v[i].z * v[i].z + v[i].w * v[i].w);
        }
    }
    // reduce within the 16 lanes of this row
#pragma unroll
    for (int o = 8; o >= 1; o >>= 1) {
        sum += __shfl_xor_sync(0xffffffffu, sum, o, 16);
        sq  += __shfl_xor_sync(0xffffffffu, sq,  o, 16);
    }
    if (lane16 == 0) {
        float mu  = sum / (float)D;
        float var = fmaxf((sq - (float)D * mu * mu) / (float)(D - 1), 0.f);
        s_mu[rowInTile]  = mu;
        s_sig[rowInTile] = sqrtf(var);
    }
    __syncthreads();

    // ---- warp 0: weighted scan over 8 rows + decoupled lookback ----
    if (tid < 32) {
        const int lane = tid;
        const int sg   = s0 + lane;             // lanes 0..7 hold real rows
        float tm = 0.f, ts = 0.f;
        if (lane < 8 && sg < S) {
            float w = powf(alpha, (float)sg);
            tm = w * s_mu[lane];
            ts = w * s_sig[lane];
        }

        // inclusive scan within warp (lanes >=8 carry zeros)
        float im = tm, is = ts;
#pragma unroll
        for (int o = 1; o < 32; o <<= 1) {
            float pm = __shfl_up_sync(0xffffffffu, im, o);
            float ps = __shfl_up_sync(0xffffffffu, is, o);
            if (lane >= o) { im += pm; is += ps; }
        }
        float aggM = __shfl_sync(0xffffffffu, im, 7);
        float aggS = __shfl_sync(0xffffffffu, is, 7);

        TileState* st = &g_state[vid];
        float runM = 0.f, runS = 0.f;

        if (j == 0) {
            if (lane == 0) {
                st->im = aggM; st->is = aggS;
                __threadfence();
                atomicExch(&st->flag, 2);
            }
        } else {
            // publish aggregate first (unblocks successors)
            if (lane == 0) {
                st->am = aggM; st->as = aggS;
                __threadfence();
                atomicExch(&st->flag, 1);
            }
            // warp-parallel lookback: lane L inspects tile j-1-offset-L
            const int baseIdx = vid - j;     // first tile of this batch
            int offset = 0;
            bool done = false;
            while (!done) {
                int pj = j - 1 - offset - lane;
                int f;
                float vm = 0.f, vs = 0.f;
                if (pj >= 0) {
                    volatile TileState* ps = &g_state[baseIdx + pj];
                    do { f = ps->flag; } while (f == 0);
                    __threadfence();
                    if (f == 2) { vm = ps->im; vs = ps->is; }
                    else        { vm = ps->am; vs = ps->as; }
                } else {
                    f = 2;  // virtual inclusive-zero before batch start
                }
                unsigned bal = __ballot_sync(0xffffffffu, f == 2);
                if (bal == 0) {
#pragma unroll
                    for (int o = 16; o >= 1; o >>= 1) {
                        vm += __shfl_xor_sync(0xffffffffu, vm, o);
                        vs += __shfl_xor_sync(0xffffffffu, vs, o);
                    }
                    runM += vm; runS += vs;
                    offset += 32;
                } else {
                    int first = __ffs(bal) - 1;   // closest inclusive
                    if (lane > first) { vm = 0.f; vs = 0.f; }
#pragma unroll
                    for (int o = 16; o >= 1; o >>= 1) {
                        vm += __shfl_xor_sync(0xffffffffu, vm, o);
                        vs += __shfl_xor_sync(0xffffffffu, vs, o);
                    }
                    runM += vm; runS += vs;
                    done = true;
                }
            }
            // publish inclusive
            if (lane == 0) {
                st->im = runM + aggM; st->is = runS + aggS;
                __threadfence();
                atomicExch(&st->flag, 2);
            }
        }

        // final per-row cumulants (lanes 0..7)
        if (lane < 8) {
            const float h_mu = h[b * 2 + 0];
            const float h_sg = h[b * 2 + 1];
            float mc = fmaf(one_minus, runM + im, alpha * h_mu);
            float sc = fmaf(one_minus, runS + is, alpha * h_sg);
            sc = fmaxf(sc, 1e-12f);
            s_rowmu[lane]  = mc;
            s_rowinv[lane] = 1.f / sc;
            if (sg == S - 1) {
                out_h[b * 2 + 0] = mc;
                out_h[b * 2 + 1] = sc;
            }
        }
    }
    __syncthreads();

    // ---- normalize from registers and store (streaming) ----
    if (rowValid) {
        const float mc  = s_rowmu[rowInTile];
        const float inv = s_rowinv[rowInTile];
#pragma unroll
        for (int i = 0; i < NF4; i++) {
            int c = lane16 + (i << 4);
            float4 g4 = s_gamma[c];
            float4 b4 = s_beta[c];
            float4 o;
            o.x = fmaf((v[i].x - mc) * inv, g4.x, b4.x);
            o.y = fmaf((v[i].y - mc) * inv, g4.y, b4.y);
            o.z = fmaf((v[i].z - mc) * inv, g4.z, b4.z);
            o.w = fmaf((v[i].w - mc) * inv, g4.w, b4.w);
            __stcs(reinterpret_cast<float4*>(y) + rowBase + c, o);
        }
    }
}

// ---------------------------------------------------------------------------
// Fallback path (proven R3 kernels) for shapes the fused kernel doesn't cover.
// ---------------------------------------------------------------------------
__global__ void row_stats_kernel(const float* __restrict__ x, int D, int nrows) {
    int warp = (blockIdx.x * blockDim.x + threadIdx.x) >> 5;
    int lane = threadIdx.x & 31;
    if (warp >= nrows) return;
    const float4* xr = reinterpret_cast<const float4*>(x) + (size_t)warp * (D >> 2);
    int nf4 = D >> 2;
    float s = 0.f, ss = 0.f;
    for (int i = lane; i < nf4; i += 32) {
        float4 v = xr[i];
        s  += (v.x + v.y) + (v.z + v.w);
        ss += (v.x * v.x + v.y * v.y) + (v.z * v.z + v.w * v.w);
    }
#pragma unroll
    for (int o = 16; o > 0; o >>= 1) {
        s  += __shfl_xor_sync(0xffffffffu, s, o);
        ss += __shfl_xor_sync(0xffffffffu, ss, o);
    }
    if (lane == 0) {
        float mu  = s / (float)D;
        float var = fmaxf((ss - (float)D * mu * mu) / (float)(D - 1), 0.f);
        g_stats[warp] = make_float2(mu, sqrtf(var));
    }
}

__global__ void scan_kernel(const float* __restrict__ h,
                            const float* __restrict__ alpha_logit,
                            float* __restrict__ out_h, int S) {
    const int b = blockIdx.x, tid = threadIdx.x;
    const int lane = tid & 31, wid = tid >> 5, nthr = blockDim.x;
    const float alpha = 1.f / (1.f + expf(-alpha_logit[0]));
    const float h_mu = h[b * 2 + 0], h_sigma = h[b * 2 + 1];
    const float one_minus = 1.f - alpha;
    const int items = (S + nthr - 1) / nthr;
    const int base = tid * items;
    float am[16], as[16];
    float sm = 0.f, sg = 0.f;
    for (int j = 0; j < items; j++) {
        int t = base + j;
        float wm = 0.f, ws = 0.f;
        if (t < S) {
            float w = powf(alpha, (float)t);
            float2 st = g_stats[b * S + t];
            wm = w * st.x; ws = w * st.y;
        }
        sm += wm; sg += ws; am[j] = sm; as[j] = sg;
    }
    float m = sm, g2 = sg;
#pragma unroll
    for (int o = 1; o < 32; o <<= 1) {
        float pm = __shfl_up_sync(0xffffffffu, m, o);
        float pg = __shfl_up_sync(0xffffffffu, g2, o);
        if (lane >= o) { m += pm; g2 += pg; }
    }
    float em = __shfl_up_sync(0xffffffffu, m, 1);
    float eg = __shfl_up_sync(0xffffffffu, g2, 1);
    if (lane == 0) { em = 0.f; eg = 0.f; }
    __shared__ float2 wtot[32];
    if (lane == 31) wtot[wid] = make_float2(m, g2);
    __syncthreads();
    if (wid == 0) {
        int nw = nthr >> 5;
        float2 vv = (lane < nw) ? wtot[lane] : make_float2(0.f, 0.f);
        float a = vv.x, c = vv.y;
#pragma unroll
        for (int o = 1; o < 32; o <<= 1) {
            float pa = __shfl_up_sync(0xffffffffu, a, o);
            float pc = __shfl_up_sync(0xffffffffu, c, o);
            if (lane >= o) { a += pa; c += pc; }
        }
        wtot[lane] = make_float2(a, c);
    }
    __syncthreads();
    float off_m = em + (wid > 0 ? wtot[wid - 1].x : 0.f);
    float off_s = eg + (wid > 0 ? wtot[wid - 1].y : 0.f);
    for (int j = 0; j < items; j++) {
        int t = base + j;
        if (t < S) {
            float mc = fmaf(one_minus, off_m + am[j], alpha * h_mu);
            float sc = fmaf(one_minus, off_s + as[j], alpha * h_sigma);
            sc = fmaxf(sc, 1e-12f);
            g_cum[b * S + t] = make_float2(mc, 1.f / sc);
            if (t == S - 1) { out_h[b * 2 + 0] = mc; out_h[b * 2 + 1] = sc; }
        }
    }
}

__global__ void norm_kernel(const float* __restrict__ x,
                            const float* __restrict__ gamma,
                            const float* __restrict__ beta,
                            float* __restrict__ y,
                            unsigned D4, unsigned n4) {
    unsigned i = blockIdx.x * blockDim.x + threadIdx.x;
    if (i >= n4) return;
    unsigned row = i / D4;
    unsigned d4  = i - row * D4;
    float4 xv = reinterpret_cast<const float4*>(x)[i];
    float2 c  = g_cum[row];
    float4 gv = reinterpret_cast<const float4*>(gamma)[d4];
    float4 bv = reinterpret_cast<const float4*>(beta)[d4];
    float4 o;
    o.x = fmaf((xv.x - c.x) * c.y, gv.x, bv.x);
    o.y = fmaf((xv.y - c.x) * c.y, gv.y, bv.y);
    o.z = fmaf((xv.z - c.x) * c.y, gv.z, bv.z);
    o.w = fmaf((xv.w - c.x) * c.y, gv.w, bv.w);
    reinterpret_cast<float4*>(y)[i] = o;
}

// ---------------------------------------------------------------------------
extern "C" void kernel_launch(void* const* d_in, const int* in_sizes, int n_in,
                              void* d_out, int out_size) {
    const float* x      = (const float*)d_in[0];
    const float* h      = (const float*)d_in[1];
    const float* gamma  = (const float*)d_in[2];
    const float* beta   = (const float*)d_in[3];
    const float* alogit = (const float*)d_in[4];

    const int nx = in_sizes[0];
    const int B  = in_sizes[1] / 2;
    const int D  = in_sizes[2];
    const int S  = nx / (B * D);
    const int nrows = B * S;

    float* y     = (float*)d_out;
    float* out_h = y + nx;

    const int tilesPerBatch = (S + 7) / 8;
    const int ntiles = B * tilesPerBatch;
    const int nf4 = D / 64;

    bool fusable = (D % 64 == 0) && (D <= 1024) && (ntiles <= MAX_TILES) &&
                   (nf4 == 2 || nf4 == 4 || nf4 == 8 || nf4 == 16) &&
                   (nrows <= MAX_ROWS);

    if (fusable) {
        init_kernel<<<(ntiles + 255) / 256, 256>>>(ntiles);
        switch (nf4) {
            case 2:  fused_kernel<2><<<ntiles, 128>>>(x, h, gamma, beta, alogit, y, out_h, S, D, tilesPerBatch); break;
            case 4:  fused_kernel<4><<<ntiles, 128>>>(x, h, gamma, beta, alogit, y, out_h, S, D, tilesPerBatch); break;
            case 8:  fused_kernel<8><<<ntiles, 128>>>(x, h, gamma, beta, alogit, y, out_h, S, D, tilesPerBatch); break;
            case 16: fused_kernel<16><<<ntiles, 128>>>(x, h, gamma, beta, alogit, y, out_h, S, D, tilesPerBatch); break;
        }
    } else {
        int wpb = 8;
        row_stats_kernel<<<(nrows + wpb - 1) / wpb, wpb * 32>>>(x, D, nrows);
        scan_kernel<<<B, 1024>>>(h, alogit, out_h, S);
        unsigned n4 = (unsigned)(nx >> 2);
        unsigned D4 = (unsigned)(D >> 2);
        int tpb = 256;
        norm_kernel<<<(n4 + tpb - 1) / tpb, tpb>>>(x, gamma, beta, y, D4, n4);
    }
}

// round 10
// speedup vs baseline: 1.4891x; 1.4891x over previous
#include <cuda_runtime.h>
#include <math.h>

// ---------------------------------------------------------------------------
// Scratch (__device__ globals; no allocation allowed).
// ---------------------------------------------------------------------------
#define MAX_ROWS (1 << 17)
__device__ float2 g_stats[MAX_ROWS];  // (mu, sigma) per row
__device__ float2 g_cum[MAX_ROWS];    // (mu_cum, 1/sigma_cum) per row

// ---------------------------------------------------------------------------
// Kernel 1: per-row mean + std (ddof=1). One warp per row of D floats.
// (Proven: 24.5us @ 71.6% DRAM on B=8,S=8192,D=512.)
// ---------------------------------------------------------------------------
__global__ void row_stats_kernel(const float* __restrict__ x, int D, int nrows) {
    int warp = (blockIdx.x * blockDim.x + threadIdx.x) >> 5;
    int lane = threadIdx.x & 31;
    if (warp >= nrows) return;

    const float4* xr = reinterpret_cast<const float4*>(x) + (size_t)warp * (D >> 2);
    int nf4 = D >> 2;
    float s = 0.f, ss = 0.f;
    for (int i = lane; i < nf4; i += 32) {
        float4 v = xr[i];
        s  += (v.x + v.y) + (v.z + v.w);
        ss += (v.x * v.x + v.y * v.y) + (v.z * v.z + v.w * v.w);
    }
#pragma unroll
    for (int o = 16; o > 0; o >>= 1) {
        s  += __shfl_xor_sync(0xffffffffu, s, o);
        ss += __shfl_xor_sync(0xffffffffu, ss, o);
    }
    if (lane == 0) {
        float mu  = s / (float)D;
        float var = fmaxf((ss - (float)D * mu * mu) / (float)(D - 1), 0.f);
        g_stats[warp] = make_float2(mu, sqrtf(var));
    }
}

// ---------------------------------------------------------------------------
// Kernel 2: per-batch weighted prefix sum over S scalars (block scan).
// ---------------------------------------------------------------------------
__global__ void scan_kernel(const float* __restrict__ h,
                            const float* __restrict__ alpha_logit,
                            float* __restrict__ out_h, int S) {
    const int b    = blockIdx.x;
    const int tid  = threadIdx.x;
    const int lane = tid & 31;
    const int wid  = tid >> 5;
    const int nthr = blockDim.x;

    const float alpha = 1.f / (1.f + expf(-alpha_logit[0]));
    const float h_mu    = h[b * 2 + 0];
    const float h_sigma = h[b * 2 + 1];
    const float one_minus = 1.f - alpha;

    const int items = (S + nthr - 1) / nthr;   // <= 16
    const int base  = tid * items;

    float am[16], as[16];
    float sm = 0.f, sg = 0.f;
    for (int j = 0; j < items; j++) {
        int t = base + j;
        float wm = 0.f, ws = 0.f;
        if (t < S) {
            float w = powf(alpha, (float)t);
            float2 st = g_stats[b * S + t];
            wm = w * st.x;
            ws = w * st.y;
        }
        sm += wm; sg += ws;
        am[j] = sm; as[j] = sg;
    }

    float m = sm, g2 = sg;
#pragma unroll
    for (int o = 1; o < 32; o <<= 1) {
        float pm = __shfl_up_sync(0xffffffffu, m, o);
        float pg = __shfl_up_sync(0xffffffffu, g2, o);
        if (lane >= o) { m += pm; g2 += pg; }
    }
    float em = __shfl_up_sync(0xffffffffu, m, 1);
    float eg = __shfl_up_sync(0xffffffffu, g2, 1);
    if (lane == 0) { em = 0.f; eg = 0.f; }

    __shared__ float2 wtot[32];
    if (lane == 31) wtot[wid] = make_float2(m, g2);
    __syncthreads();
    if (wid == 0) {
        int nw = nthr >> 5;
        float2 v = (lane < nw) ? wtot[lane] : make_float2(0.f, 0.f);
        float a = v.x, c = v.y;
#pragma unroll
        for (int o = 1; o < 32; o <<= 1) {
            float pa = __shfl_up_sync(0xffffffffu, a, o);
            float pc = __shfl_up_sync(0xffffffffu, c, o);
            if (lane >= o) { a += pa; c += pc; }
        }
        wtot[lane] = make_float2(a, c);
    }
    __syncthreads();

    float off_m = em + (wid > 0 ? wtot[wid - 1].x : 0.f);
    float off_s = eg + (wid > 0 ? wtot[wid - 1].y : 0.f);

    for (int j = 0; j < items; j++) {
        int t = base + j;
        if (t < S) {
            float mc = fmaf(one_minus, off_m + am[j], alpha * h_mu);
            float sc = fmaf(one_minus, off_s + as[j], alpha * h_sigma);
            sc = fmaxf(sc, 1e-12f);
            g_cum[b * S + t] = make_float2(mc, 1.f / sc);
            if (t == S - 1) {
                out_h[b * 2 + 0] = mc;
                out_h[b * 2 + 1] = sc;
            }
        }
    }
}

// ---------------------------------------------------------------------------
// Kernel 3: normalize, float4 vectorized, REVERSED row order.
// The stats kernel just streamed x front-to-back, so L2 (~126MB vs x=134MB)
// holds the tail of x. Processing rows high->low turns those into L2 hits.
//   __ldlu on x : last-use; hits consume the line, misses fill evict-first.
//   __stcs on y : streaming store; y traffic doesn't evict resident x.
// d4shift >= 0: D4 power of two (shift/mask); else generic divide.
// ---------------------------------------------------------------------------
__global__ void norm_kernel(const float* __restrict__ x,
                            const float* __restrict__ gamma,
                            const float* __restrict__ beta,
                            float* __restrict__ y,
                            unsigned D4, int d4shift,
                            unsigned nrows, unsigned n4) {
    unsigned i = blockIdx.x * blockDim.x + threadIdx.x;
    if (i >= n4) return;

    unsigned row, d4;
    if (d4shift >= 0) {
        row = i >> d4shift;
        d4  = i & (D4 - 1u);
    } else {
        row = i / D4;
        d4  = i - row * D4;
    }
    // reverse: CTA/thread order ascends, rows descend -> chase L2 tail of x
    unsigned rrow = nrows - 1u - row;
    size_t idx = (size_t)rrow * D4 + d4;

    float4 xv = __ldlu(reinterpret_cast<const float4*>(x) + idx);
    float2 c  = g_cum[rrow];
    float4 gv = reinterpret_cast<const float4*>(gamma)[d4];
    float4 bv = reinterpret_cast<const float4*>(beta)[d4];

    float4 o;
    o.x = fmaf((xv.x - c.x) * c.y, gv.x, bv.x);
    o.y = fmaf((xv.y - c.x) * c.y, gv.y, bv.y);
    o.z = fmaf((xv.z - c.x) * c.y, gv.z, bv.z);
    o.w = fmaf((xv.w - c.x) * c.y, gv.w, bv.w);
    __stcs(reinterpret_cast<float4*>(y) + idx, o);
}

// ---------------------------------------------------------------------------
extern "C" void kernel_launch(void* const* d_in, const int* in_sizes, int n_in,
                              void* d_out, int out_size) {
    const float* x      = (const float*)d_in[0];
    const float* h      = (const float*)d_in[1];
    const float* gamma  = (const float*)d_in[2];
    const float* beta   = (const float*)d_in[3];
    const float* alogit = (const float*)d_in[4];

    const int nx = in_sizes[0];          // B*S*D
    const int B  = in_sizes[1] / 2;      // h is (B,1,2)
    const int D  = in_sizes[2];          // gamma length
    const int S  = nx / (B * D);
    const int nrows = B * S;

    float* y     = (float*)d_out;
    float* out_h = y + nx;

    // Kernel 1: one warp per row, 8 warps/block (proven)
    {
        int wpb = 8;
        int blocks = (nrows + wpb - 1) / wpb;
        row_stats_kernel<<<blocks, wpb * 32>>>(x, D, nrows);
    }
    // Kernel 2: one block per batch
    scan_kernel<<<B, 1024>>>(h, alogit, out_h, S);

    // Kernel 3: elementwise normalize, reversed row order
    {
        unsigned n4 = (unsigned)(nx >> 2);
        unsigned D4 = (unsigned)(D >> 2);
        int d4shift = -1;
        if ((D4 & (D4 - 1u)) == 0u) {
            d4shift = 0;
            while ((1u << d4shift) < D4) d4shift++;
        }
        int tpb = 256;
        unsigned nb = (n4 + tpb - 1) / tpb;
        norm_kernel<<<nb, tpb>>>(x, gamma, beta, y, D4, d4shift,
                                 (unsigned)nrows, n4);
    }
}